// round 14
// baseline (speedup 1.0000x reference)
#include <cuda_runtime.h>

#define BATCHES 4
#define MBOX    128
#define TPB     512
#define PPT     2
#define GRIDW   32
#define NCELL   (GRIDW * GRIDW)
#define CAPE    15    // packed entries per cell row; overflow -> brute fallback
#define BOXF    7     // floats per box

// Extract byte j (0..15) of a uint4, low 7 bits.
__device__ __forceinline__ int pick_box(uint4 v, int j)
{
    unsigned lo = __byte_perm(v.x, v.y, j);        // valid for j in 0..7
    unsigned hi = __byte_perm(v.z, v.w, j & 7);    // j-8 for j in 8..15
    unsigned r  = (j < 8) ? lo : hi;
    return (int)(r & 127u);
}

__global__ __launch_bounds__(TPB)
void pib_fused(const float* __restrict__ pts,
               const float* __restrict__ boxes,
               float* __restrict__ out,
               int N)
{
    // Preprocessed boxes:
    //   sA[m] = (cx, cy, cos, sin)
    //   sB[m] = (hx, hy, cz, hz)
    __shared__ float4 sA[MBOX];
    __shared__ float4 sB[MBOX];
    __shared__ int    cnt[NCELL];
    __shared__ uint4  rows[NCELL];   // byte0=count, bytes1..15=box indices
    __shared__ float  sRaw[MBOX * BOXF];          // coalesced staging (3.5 KB)

    const int bpb = gridDim.x / BATCHES;     // 64
    const int b   = blockIdx.x / bpb;
    const int blk = blockIdx.x % bpb;
    const int t   = threadIdx.x;

    const float inv_cell  = (float)GRIDW / 100.0f;   // 0.32
    const float cell_sz   = 100.0f / (float)GRIDW;   // 3.125
    const float cell_half = 0.5f * cell_sz;          // 1.5625
    const float org       = -50.0f;

    // ---- hoisted: issue point loads FIRST so their latency overlaps the
    //      table build (ptxas will not hoist LDG across the barrier itself).
    const int i0 = (blk * TPB + t) * PPT;
    const float2* p2 = reinterpret_cast<const float2*>(pts + ((size_t)b * N + i0) * 3);
    float2 qa = p2[0], qb = p2[1], qc = p2[2];

    // Zero counters + coalesced box staging. (rows need no zeroing: the count
    // byte is injected after the build; stale entry bytes are correct-neutral.)
    {
        if (t < NCELL / 4) {
            int4 zz = make_int4(0, 0, 0, 0);
            reinterpret_cast<int4*>(cnt)[t] = zz;
        }
        const float* src = boxes + (size_t)b * MBOX * BOXF;
        #pragma unroll
        for (int k = t; k < MBOX * BOXF; k += TPB)
            sRaw[k] = src[k];
    }
    __syncthreads();

    // ---- build: FOUR threads per box (row range split 4 ways).
    //      SAT-exact registration: AABB candidate cells are kept only if the
    //      rotated rect actually intersects the cell (two rect-axis tests;
    //      the x/y-axis tests are implied by the AABB range). A box that
    //      contains a point in cell C intersects C, and thresholds carry
    //      +1e-3 m slack >> fp error, so no containing box is ever dropped.
    {
        const int boxm   = t & (MBOX - 1);        // t % 128
        const int quarid = t >> 7;                // 0..3: row-range quarter
        const float* bx = &sRaw[boxm * BOXF];
        float cx = bx[0], cy = bx[1], cz = bx[2];
        float hx = 0.5f * bx[3], hy = 0.5f * bx[4], hz = 0.5f * bx[5];
        float s, c;
        __sincosf(bx[6], &s, &c);
        if (quarid == 0) {
            sA[boxm] = make_float4(cx, cy, c, s);
            sB[boxm] = make_float4(hx, hy, cz, hz);
        }

        float ac = fabsf(c), as = fabsf(s);
        float ex = hx * ac + hy * as + 1e-3f;
        float ey = hx * as + hy * ac + 1e-3f;
        float rc = cell_half * (ac + as);         // cell half-extent on rect axes
        float thu = hx + rc + 1e-3f;
        float thv = hy + rc + 1e-3f;

        int xlo = min(max((int)floorf((cx - ex - org) * inv_cell), 0), GRIDW - 1);
        int xhi = min(max((int)floorf((cx + ex - org) * inv_cell), 0), GRIDW - 1);
        int ylo = min(max((int)floorf((cy - ey - org) * inv_cell), 0), GRIDW - 1);
        int yhi = min(max((int)floorf((cy + ey - org) * inv_cell), 0), GRIDW - 1);

        // Split rows among the four threads handling this box.
        int nrows = yhi - ylo + 1;                // 1..GRIDW
        int per   = (nrows + 3) >> 2;             // ceil(nrows/4)
        int y0 = ylo + quarid * per;
        int y1 = min(y0 + per - 1, yhi);

        for (int yy = y0; yy <= y1; ++yy) {
            float qcy = org + ((float)yy + 0.5f) * cell_sz;
            float ddy = qcy - cy;
            for (int xx = xlo; xx <= xhi; ++xx) {
                float qcx = org + ((float)xx + 0.5f) * cell_sz;
                float ddx = qcx - cx;
                // Rect-axis SAT tests (u=(c,s), v=(-s,c)).
                float du = ddx * c + ddy * s;
                float dv = ddy * c - ddx * s;
                if ((fabsf(du) <= thu) & (fabsf(dv) <= thv)) {
                    int cell = yy * GRIDW + xx;
                    int pp = atomicAdd(&cnt[cell], 1);
                    if (pp < CAPE)
                        reinterpret_cast<unsigned char*>(&rows[cell])[1 + pp] =
                            (unsigned char)boxm;
                }
            }
        }
    }

    // Cell indices computed from already-arrived registers (overlaps build).
    float x0 = qa.x, y0p = qa.y, z0 = qb.x;
    float x1 = qb.y, y1p = qc.x, z1 = qc.y;

    int ix0 = min(max((int)floorf((x0 - org) * inv_cell), 0), GRIDW - 1);
    int iy0 = min(max((int)floorf((y0p - org) * inv_cell), 0), GRIDW - 1);
    int ix1 = min(max((int)floorf((x1 - org) * inv_cell), 0), GRIDW - 1);
    int iy1 = min(max((int)floorf((y1p - org) * inv_cell), 0), GRIDW - 1);
    int cell0 = iy0 * GRIDW + ix0;
    int cell1 = iy1 * GRIDW + ix1;

    __syncthreads();

    // ---- inject counts into byte 0 of each packed row (2 cells/thread) ----
    #pragma unroll
    for (int c = t; c < NCELL; c += TPB) {
        int n = cnt[c];
        reinterpret_cast<unsigned char*>(&rows[c])[0] =
            (unsigned char)min(n, 255);
    }
    __syncthreads();

    // ---- query: two points per thread, one LDS.128 per point, guard-free --
    // Safety: testing ANY box index is correct-neutral (a true hit implies
    // the box is in the point's cell list, so min() is unchanged; a false
    // hit contributes nothing). Hence stale entry bytes are harmless.
    uint4 v0 = rows[cell0];
    uint4 v1 = rows[cell1];
    int n0 = (int)(v0.x & 0xFFu);
    int n1 = (int)(v1.x & 0xFFu);

    int l0 = (n0 <= CAPE) ? n0 : 0;
    int l1 = (n1 <= CAPE) ? n1 : 0;
    int nmax = max(l0, l1);                       // <= CAPE

    int best0 = MBOX, best1 = MBOX;

    for (int j = 1; j <= nmax; ++j) {
        {
            int m = pick_box(v0, j);
            float4 A  = sA[m];
            float4 Bv = sB[m];
            float dx = x0 - A.x, dy = y0p - A.y, dz = z0 - Bv.z;
            float lx = dx * A.z + dy * A.w;
            float ly = dy * A.z - dx * A.w;
            bool in = (fabsf(lx) <= Bv.x) & (fabsf(ly) <= Bv.y) & (fabsf(dz) <= Bv.w);
            best0 = min(best0, in ? m : MBOX);
        }
        {
            int m = pick_box(v1, j);
            float4 A  = sA[m];
            float4 Bv = sB[m];
            float dx = x1 - A.x, dy = y1p - A.y, dz = z1 - Bv.z;
            float lx = dx * A.z + dy * A.w;
            float ly = dy * A.z - dx * A.w;
            bool in = (fabsf(lx) <= Bv.x) & (fabsf(ly) <= Bv.y) & (fabsf(dz) <= Bv.w);
            best1 = min(best1, in ? m : MBOX);
        }
    }

    // Structural overflow fallback: test every box (never skips a hit).
    if ((n0 > CAPE) | (n1 > CAPE)) {
        for (int m = 0; m < MBOX; ++m) {
            float4 A  = sA[m];
            float4 Bv = sB[m];
            if (n0 > CAPE) {
                float dx = x0 - A.x, dy = y0p - A.y, dz = z0 - Bv.z;
                float lx = dx * A.z + dy * A.w;
                float ly = dy * A.z - dx * A.w;
                bool in = (fabsf(lx) <= Bv.x) & (fabsf(ly) <= Bv.y) & (fabsf(dz) <= Bv.w);
                best0 = min(best0, in ? m : MBOX);
            }
            if (n1 > CAPE) {
                float dx = x1 - A.x, dy = y1p - A.y, dz = z1 - Bv.z;
                float lx = dx * A.z + dy * A.w;
                float ly = dy * A.z - dx * A.w;
                bool in = (fabsf(lx) <= Bv.x) & (fabsf(ly) <= Bv.y) & (fabsf(dz) <= Bv.w);
                best1 = min(best1, in ? m : MBOX);
            }
        }
    }

    float2 o = make_float2((best0 == MBOX) ? -1.0f : (float)best0,
                           (best1 == MBOX) ? -1.0f : (float)best1);
    *reinterpret_cast<float2*>(out + (size_t)b * N + i0) = o;
}

extern "C" void kernel_launch(void* const* d_in, const int* in_sizes, int n_in,
                              void* d_out, int out_size)
{
    const float* pts   = (const float*)d_in[0];
    const float* boxes = (const float*)d_in[1];
    float* out = (float*)d_out;

    const int N = out_size / BATCHES;                 // 65536
    const int grid = BATCHES * (N / (TPB * PPT));     // 4 * 64 = 256 blocks
    pib_fused<<<grid, TPB>>>(pts, boxes, out, N);
}

// round 15
// speedup vs baseline: 1.0109x; 1.0109x over previous
#include <cuda_runtime.h>

#define BATCHES 4
#define MBOX    128
#define TPB     512
#define PPT     2
#define GRIDW   32
#define NCELL   (GRIDW * GRIDW)
#define CAP     16    // list entries per cell; overflow -> brute-force fallback
#define BOXF    7     // floats per box

// Extract byte j (0..15) of a uint4, low 7 bits.
__device__ __forceinline__ int pick_box(uint4 v, int j)
{
    unsigned lo = __byte_perm(v.x, v.y, j);        // valid for j in 0..7
    unsigned hi = __byte_perm(v.z, v.w, j & 7);    // j-8 for j in 8..15
    unsigned r  = (j < 8) ? lo : hi;
    return (int)(r & 127u);
}

__global__ __launch_bounds__(TPB)
void pib_fused(const float* __restrict__ pts,
               const float* __restrict__ boxes,
               float* __restrict__ out,
               int N)
{
    // Preprocessed boxes:
    //   sA[m] = (cx, cy, cos, sin)
    //   sB[m] = (hx, hy, cz, hz)
    __shared__ float4 sA[MBOX];
    __shared__ float4 sB[MBOX];
    __shared__ int    cnt[NCELL];
    __shared__ unsigned char lst[NCELL][CAP];     // 16B rows -> one LDS.128
    __shared__ float  sRaw[MBOX * BOXF];          // coalesced staging (3.5 KB)

    const int bpb = gridDim.x / BATCHES;     // 64
    const int b   = blockIdx.x / bpb;
    const int blk = blockIdx.x % bpb;
    const int t   = threadIdx.x;

    const float inv_cell  = (float)GRIDW / 100.0f;   // 0.32
    const float cell_sz   = 100.0f / (float)GRIDW;   // 3.125
    const float cell_half = 0.5f * cell_sz;          // 1.5625
    const float org       = -50.0f;

    // ---- hoisted: issue point loads FIRST so their latency overlaps the
    //      table build (ptxas will not hoist LDG across the barrier itself).
    const int i0 = (blk * TPB + t) * PPT;
    const float2* p2 = reinterpret_cast<const float2*>(pts + ((size_t)b * N + i0) * 3);
    float2 qa = p2[0], qb = p2[1], qc = p2[2];

    // Zero counters + coalesced box staging. (lst needs no zeroing: entries
    // past a cell's count are never trusted — garbage tests are correct-
    // neutral, see query comment.)
    {
        if (t < NCELL / 4) {
            int4 zz = make_int4(0, 0, 0, 0);
            reinterpret_cast<int4*>(cnt)[t] = zz;
        }
        const float* src = boxes + (size_t)b * MBOX * BOXF;
        #pragma unroll
        for (int k = t; k < MBOX * BOXF; k += TPB)
            sRaw[k] = src[k];
    }
    __syncthreads();

    // ---- build: FOUR threads per box (row range split 4 ways).
    //      SAT-exact registration: AABB candidate cells are kept only if the
    //      rotated rect actually intersects the cell (two rect-axis tests;
    //      the x/y-axis tests are implied by the AABB range). A box that
    //      contains a point in cell C intersects C, and thresholds carry
    //      +1e-3 m slack >> fp error, so no containing box is ever dropped.
    {
        const int boxm   = t & (MBOX - 1);        // t % 128
        const int quarid = t >> 7;                // 0..3: row-range quarter
        const float* bx = &sRaw[boxm * BOXF];
        float cx = bx[0], cy = bx[1], cz = bx[2];
        float hx = 0.5f * bx[3], hy = 0.5f * bx[4], hz = 0.5f * bx[5];
        float s, c;
        __sincosf(bx[6], &s, &c);
        if (quarid == 0) {
            sA[boxm] = make_float4(cx, cy, c, s);
            sB[boxm] = make_float4(hx, hy, cz, hz);
        }

        float ac = fabsf(c), as = fabsf(s);
        float ex = hx * ac + hy * as + 1e-3f;
        float ey = hx * as + hy * ac + 1e-3f;
        float rc = cell_half * (ac + as);         // cell half-extent on rect axes
        float thu = hx + rc + 1e-3f;
        float thv = hy + rc + 1e-3f;

        int xlo = min(max((int)floorf((cx - ex - org) * inv_cell), 0), GRIDW - 1);
        int xhi = min(max((int)floorf((cx + ex - org) * inv_cell), 0), GRIDW - 1);
        int ylo = min(max((int)floorf((cy - ey - org) * inv_cell), 0), GRIDW - 1);
        int yhi = min(max((int)floorf((cy + ey - org) * inv_cell), 0), GRIDW - 1);

        // Split rows among the four threads handling this box.
        int nrows = yhi - ylo + 1;                // 1..GRIDW
        int per   = (nrows + 3) >> 2;             // ceil(nrows/4)
        int y0 = ylo + quarid * per;
        int y1 = min(y0 + per - 1, yhi);

        for (int yy = y0; yy <= y1; ++yy) {
            float qcy = org + ((float)yy + 0.5f) * cell_sz;
            float ddy = qcy - cy;
            for (int xx = xlo; xx <= xhi; ++xx) {
                float qcx = org + ((float)xx + 0.5f) * cell_sz;
                float ddx = qcx - cx;
                // Rect-axis SAT tests (u=(c,s), v=(-s,c)).
                float du = ddx * c + ddy * s;
                float dv = ddy * c - ddx * s;
                if ((fabsf(du) <= thu) & (fabsf(dv) <= thv)) {
                    int cell = yy * GRIDW + xx;
                    int pp = atomicAdd(&cnt[cell], 1);
                    if (pp < CAP) lst[cell][pp] = (unsigned char)boxm;
                }
            }
        }
    }

    // Cell indices computed from already-arrived registers (overlaps build).
    float x0 = qa.x, y0p = qa.y, z0 = qb.x;
    float x1 = qb.y, y1p = qc.x, z1 = qc.y;

    int ix0 = min(max((int)floorf((x0 - org) * inv_cell), 0), GRIDW - 1);
    int iy0 = min(max((int)floorf((y0p - org) * inv_cell), 0), GRIDW - 1);
    int ix1 = min(max((int)floorf((x1 - org) * inv_cell), 0), GRIDW - 1);
    int iy1 = min(max((int)floorf((y1p - org) * inv_cell), 0), GRIDW - 1);
    int cell0 = iy0 * GRIDW + ix0;
    int cell1 = iy1 * GRIDW + ix1;

    __syncthreads();

    // ---- query: two points per thread. Count and full 16B list row are
    //      loaded back-to-back (independent addresses -> overlapped latency);
    //      entries are then extracted from registers, so the loop touches
    //      only sA/sB in shared.
    // Safety: testing ANY box index is correct-neutral (a true hit implies
    // the box is in the point's cell list, so min() is unchanged; a false
    // hit contributes nothing). Hence bytes past the count are harmless.
    int  n0 = cnt[cell0];
    int  n1 = cnt[cell1];
    uint4 v0 = *reinterpret_cast<const uint4*>(&lst[cell0][0]);
    uint4 v1 = *reinterpret_cast<const uint4*>(&lst[cell1][0]);

    int l0 = (n0 <= CAP) ? n0 : 0;
    int l1 = (n1 <= CAP) ? n1 : 0;
    int nmax = max(l0, l1);                       // <= CAP

    int best0 = MBOX, best1 = MBOX;

    for (int j = 0; j < nmax; ++j) {
        {
            int m = pick_box(v0, j);
            float4 A  = sA[m];
            float4 Bv = sB[m];
            float dx = x0 - A.x, dy = y0p - A.y, dz = z0 - Bv.z;
            float lx = dx * A.z + dy * A.w;
            float ly = dy * A.z - dx * A.w;
            bool in = (fabsf(lx) <= Bv.x) & (fabsf(ly) <= Bv.y) & (fabsf(dz) <= Bv.w);
            best0 = min(best0, in ? m : MBOX);
        }
        {
            int m = pick_box(v1, j);
            float4 A  = sA[m];
            float4 Bv = sB[m];
            float dx = x1 - A.x, dy = y1p - A.y, dz = z1 - Bv.z;
            float lx = dx * A.z + dy * A.w;
            float ly = dy * A.z - dx * A.w;
            bool in = (fabsf(lx) <= Bv.x) & (fabsf(ly) <= Bv.y) & (fabsf(dz) <= Bv.w);
            best1 = min(best1, in ? m : MBOX);
        }
    }

    // Structural overflow fallback: test every box (never skips a hit).
    if ((n0 > CAP) | (n1 > CAP)) {
        for (int m = 0; m < MBOX; ++m) {
            float4 A  = sA[m];
            float4 Bv = sB[m];
            if (n0 > CAP) {
                float dx = x0 - A.x, dy = y0p - A.y, dz = z0 - Bv.z;
                float lx = dx * A.z + dy * A.w;
                float ly = dy * A.z - dx * A.w;
                bool in = (fabsf(lx) <= Bv.x) & (fabsf(ly) <= Bv.y) & (fabsf(dz) <= Bv.w);
                best0 = min(best0, in ? m : MBOX);
            }
            if (n1 > CAP) {
                float dx = x1 - A.x, dy = y1p - A.y, dz = z1 - Bv.z;
                float lx = dx * A.z + dy * A.w;
                float ly = dy * A.z - dx * A.w;
                bool in = (fabsf(lx) <= Bv.x) & (fabsf(ly) <= Bv.y) & (fabsf(dz) <= Bv.w);
                best1 = min(best1, in ? m : MBOX);
            }
        }
    }

    float2 o = make_float2((best0 == MBOX) ? -1.0f : (float)best0,
                           (best1 == MBOX) ? -1.0f : (float)best1);
    *reinterpret_cast<float2*>(out + (size_t)b * N + i0) = o;
}

extern "C" void kernel_launch(void* const* d_in, const int* in_sizes, int n_in,
                              void* d_out, int out_size)
{
    const float* pts   = (const float*)d_in[0];
    const float* boxes = (const float*)d_in[1];
    float* out = (float*)d_out;

    const int N = out_size / BATCHES;                 // 65536
    const int grid = BATCHES * (N / (TPB * PPT));     // 4 * 64 = 256 blocks
    pib_fused<<<grid, TPB>>>(pts, boxes, out, N);
}

// round 16
// speedup vs baseline: 1.0817x; 1.0700x over previous
#include <cuda_runtime.h>

#define BATCHES 4
#define MBOX    128
#define TPB     512
#define PPT     2
#define GRIDW   32
#define NCELL   (GRIDW * GRIDW)
#define CAP     16    // list entries per cell; overflow -> brute-force fallback
#define BOXF    7     // floats per box

__global__ __launch_bounds__(TPB)
void pib_fused(const float* __restrict__ pts,
               const float* __restrict__ boxes,
               float* __restrict__ out,
               int N)
{
    // Preprocessed boxes:
    //   sA[m] = (cx, cy, cos, sin)
    //   sB[m] = (hx, hy, cz, hz)
    __shared__ float4 sA[MBOX];
    __shared__ float4 sB[MBOX];
    __shared__ int    cnt[NCELL];
    __shared__ unsigned char lst[NCELL][CAP];
    __shared__ float  sRaw[MBOX * BOXF];          // coalesced staging (3.5 KB)

    const int bpb = gridDim.x / BATCHES;     // 64
    const int b   = blockIdx.x / bpb;
    const int blk = blockIdx.x % bpb;
    const int t   = threadIdx.x;

    const float inv_cell  = (float)GRIDW / 100.0f;   // 0.32
    const float cell_sz   = 100.0f / (float)GRIDW;   // 3.125
    const float cell_half = 0.5f * cell_sz;          // 1.5625
    const float org       = -50.0f;

    // ---- hoisted: issue point loads FIRST so their latency overlaps the
    //      table build (ptxas will not hoist LDG across the barrier itself).
    const int i0 = (blk * TPB + t) * PPT;
    const float2* p2 = reinterpret_cast<const float2*>(pts + ((size_t)b * N + i0) * 3);
    float2 qa = p2[0], qb = p2[1], qc = p2[2];

    // Zero counters + coalesced box staging. (lst needs no zeroing: entries
    // past a cell's count are garbage-neutral, see query comment.)
    {
        if (t < NCELL / 4) {
            int4 zz = make_int4(0, 0, 0, 0);
            reinterpret_cast<int4*>(cnt)[t] = zz;
        }
        const float* src = boxes + (size_t)b * MBOX * BOXF;
        #pragma unroll
        for (int k = t; k < MBOX * BOXF; k += TPB)
            sRaw[k] = src[k];
    }
    __syncthreads();

    // ---- build: FOUR threads per box (row range split 4 ways).
    //      SAT-exact registration: AABB candidate cells are kept only if the
    //      rotated rect actually intersects the cell (two rect-axis tests;
    //      the x/y-axis tests are implied by the AABB range). A box that
    //      contains a point in cell C intersects C, and thresholds carry
    //      +1e-3 m slack >> fp error, so no containing box is ever dropped.
    {
        const int boxm   = t & (MBOX - 1);        // t % 128
        const int quarid = t >> 7;                // 0..3: row-range quarter
        const float* bx = &sRaw[boxm * BOXF];
        float cx = bx[0], cy = bx[1], cz = bx[2];
        float hx = 0.5f * bx[3], hy = 0.5f * bx[4], hz = 0.5f * bx[5];
        float s, c;
        __sincosf(bx[6], &s, &c);
        if (quarid == 0) {
            sA[boxm] = make_float4(cx, cy, c, s);
            sB[boxm] = make_float4(hx, hy, cz, hz);
        }

        float ac = fabsf(c), as = fabsf(s);
        float ex = hx * ac + hy * as + 1e-3f;
        float ey = hx * as + hy * ac + 1e-3f;
        float rc = cell_half * (ac + as);         // cell half-extent on rect axes
        float thu = hx + rc + 1e-3f;
        float thv = hy + rc + 1e-3f;

        int xlo = min(max((int)floorf((cx - ex - org) * inv_cell), 0), GRIDW - 1);
        int xhi = min(max((int)floorf((cx + ex - org) * inv_cell), 0), GRIDW - 1);
        int ylo = min(max((int)floorf((cy - ey - org) * inv_cell), 0), GRIDW - 1);
        int yhi = min(max((int)floorf((cy + ey - org) * inv_cell), 0), GRIDW - 1);

        // Split rows among the four threads handling this box.
        int nrows = yhi - ylo + 1;                // 1..GRIDW
        int per   = (nrows + 3) >> 2;             // ceil(nrows/4)
        int y0 = ylo + quarid * per;
        int y1 = min(y0 + per - 1, yhi);

        for (int yy = y0; yy <= y1; ++yy) {
            float qcy = org + ((float)yy + 0.5f) * cell_sz;
            float ddy = qcy - cy;
            for (int xx = xlo; xx <= xhi; ++xx) {
                float qcx = org + ((float)xx + 0.5f) * cell_sz;
                float ddx = qcx - cx;
                // Rect-axis SAT tests (u=(c,s), v=(-s,c)).
                float du = ddx * c + ddy * s;
                float dv = ddy * c - ddx * s;
                if ((fabsf(du) <= thu) & (fabsf(dv) <= thv)) {
                    int cell = yy * GRIDW + xx;
                    int pp = atomicAdd(&cnt[cell], 1);
                    if (pp < CAP) lst[cell][pp] = (unsigned char)boxm;
                }
            }
        }
    }

    // Cell indices computed from already-arrived registers (overlaps build).
    float x0 = qa.x, y0p = qa.y, z0 = qb.x;
    float x1 = qb.y, y1p = qc.x, z1 = qc.y;

    int ix0 = min(max((int)floorf((x0 - org) * inv_cell), 0), GRIDW - 1);
    int iy0 = min(max((int)floorf((y0p - org) * inv_cell), 0), GRIDW - 1);
    int ix1 = min(max((int)floorf((x1 - org) * inv_cell), 0), GRIDW - 1);
    int iy1 = min(max((int)floorf((y1p - org) * inv_cell), 0), GRIDW - 1);
    int cell0 = iy0 * GRIDW + ix0;
    int cell1 = iy1 * GRIDW + ix1;

    __syncthreads();

    // ---- query: two points per thread, interleaved, guard-free ----
    // Safety: evaluating the exact test against ANY box index is correct-
    // neutral (a true hit implies the box is in the point's cell list, so
    // min() is unchanged; a false hit contributes nothing). Hence entries
    // past a cell's count may be garbage; we only clamp to &127 for bounds.
    //
    // The first ushort of each list is prefetched UNCONDITIONALLY, back-to-
    // back with the count loads (independent addresses -> all four LDS
    // overlap), and iteration 0 is peeled to consume it. This removes the
    // exposed cnt -> lst serialization on the dominant n<=2 path.
    int n0 = cnt[cell0];
    int n1 = cnt[cell1];
    unsigned short pu0 = *reinterpret_cast<const unsigned short*>(&lst[cell0][0]);
    unsigned short pu1 = *reinterpret_cast<const unsigned short*>(&lst[cell1][0]);

    int l0 = (n0 <= CAP) ? n0 : 0;
    int l1 = (n1 <= CAP) ? n1 : 0;
    int nmax = (max(l0, l1) + 1) & ~1;            // <= CAP, multiple of 2

    int best0 = MBOX, best1 = MBOX;

    // Peeled iteration j=0 (uses prefetched list words).
    if (nmax > 0) {
        #pragma unroll
        for (int k = 0; k < 2; ++k) {
            {
                int m = (pu0 >> (8 * k)) & 127;
                float4 A  = sA[m];
                float4 Bv = sB[m];
                float dx = x0 - A.x, dy = y0p - A.y, dz = z0 - Bv.z;
                float lx = dx * A.z + dy * A.w;
                float ly = dy * A.z - dx * A.w;
                bool in = (fabsf(lx) <= Bv.x) & (fabsf(ly) <= Bv.y) & (fabsf(dz) <= Bv.w);
                best0 = min(best0, in ? m : MBOX);
            }
            {
                int m = (pu1 >> (8 * k)) & 127;
                float4 A  = sA[m];
                float4 Bv = sB[m];
                float dx = x1 - A.x, dy = y1p - A.y, dz = z1 - Bv.z;
                float lx = dx * A.z + dy * A.w;
                float ly = dy * A.z - dx * A.w;
                bool in = (fabsf(lx) <= Bv.x) & (fabsf(ly) <= Bv.y) & (fabsf(dz) <= Bv.w);
                best1 = min(best1, in ? m : MBOX);
            }
        }
    }

    for (int j = 2; j < nmax; j += 2) {
        unsigned short u0 = *reinterpret_cast<const unsigned short*>(&lst[cell0][j]);
        unsigned short u1 = *reinterpret_cast<const unsigned short*>(&lst[cell1][j]);
        #pragma unroll
        for (int k = 0; k < 2; ++k) {
            {
                int m = (u0 >> (8 * k)) & 127;
                float4 A  = sA[m];
                float4 Bv = sB[m];
                float dx = x0 - A.x, dy = y0p - A.y, dz = z0 - Bv.z;
                float lx = dx * A.z + dy * A.w;
                float ly = dy * A.z - dx * A.w;
                bool in = (fabsf(lx) <= Bv.x) & (fabsf(ly) <= Bv.y) & (fabsf(dz) <= Bv.w);
                best0 = min(best0, in ? m : MBOX);
            }
            {
                int m = (u1 >> (8 * k)) & 127;
                float4 A  = sA[m];
                float4 Bv = sB[m];
                float dx = x1 - A.x, dy = y1p - A.y, dz = z1 - Bv.z;
                float lx = dx * A.z + dy * A.w;
                float ly = dy * A.z - dx * A.w;
                bool in = (fabsf(lx) <= Bv.x) & (fabsf(ly) <= Bv.y) & (fabsf(dz) <= Bv.w);
                best1 = min(best1, in ? m : MBOX);
            }
        }
    }

    // Structural overflow fallback: test every box (never skips a hit).
    if ((n0 > CAP) | (n1 > CAP)) {
        for (int m = 0; m < MBOX; ++m) {
            float4 A  = sA[m];
            float4 Bv = sB[m];
            if (n0 > CAP) {
                float dx = x0 - A.x, dy = y0p - A.y, dz = z0 - Bv.z;
                float lx = dx * A.z + dy * A.w;
                float ly = dy * A.z - dx * A.w;
                bool in = (fabsf(lx) <= Bv.x) & (fabsf(ly) <= Bv.y) & (fabsf(dz) <= Bv.w);
                best0 = min(best0, in ? m : MBOX);
            }
            if (n1 > CAP) {
                float dx = x1 - A.x, dy = y1p - A.y, dz = z1 - Bv.z;
                float lx = dx * A.z + dy * A.w;
                float ly = dy * A.z - dx * A.w;
                bool in = (fabsf(lx) <= Bv.x) & (fabsf(ly) <= Bv.y) & (fabsf(dz) <= Bv.w);
                best1 = min(best1, in ? m : MBOX);
            }
        }
    }

    float2 o = make_float2((best0 == MBOX) ? -1.0f : (float)best0,
                           (best1 == MBOX) ? -1.0f : (float)best1);
    *reinterpret_cast<float2*>(out + (size_t)b * N + i0) = o;
}

extern "C" void kernel_launch(void* const* d_in, const int* in_sizes, int n_in,
                              void* d_out, int out_size)
{
    const float* pts   = (const float*)d_in[0];
    const float* boxes = (const float*)d_in[1];
    float* out = (float*)d_out;

    const int N = out_size / BATCHES;                 // 65536
    const int grid = BATCHES * (N / (TPB * PPT));     // 4 * 64 = 256 blocks
    pib_fused<<<grid, TPB>>>(pts, boxes, out, N);
}

// round 17
// speedup vs baseline: 1.0859x; 1.0039x over previous
#include <cuda_runtime.h>

#define BATCHES 4
#define MBOX    128
#define TPB     512
#define PPT     2
#define GRIDW   32
#define NCELL   (GRIDW * GRIDW)
#define CAP     16    // smem list cap; overflow handled by brute-force fallback
#define BOXF    7     // floats per box

__global__ __launch_bounds__(TPB)
void pib_fused(const float* __restrict__ pts,
               const float* __restrict__ boxes,
               float* __restrict__ out,
               int N)
{
    // Preprocessed boxes:
    //   sA[m] = (cx, cy, cos, sin)
    //   sB[m] = (hx, hy, cz, hz)
    __shared__ float4 sA[MBOX];
    __shared__ float4 sB[MBOX];
    __shared__ int    cnt[NCELL];
    __shared__ unsigned char lst[NCELL][CAP];
    __shared__ float  sRaw[MBOX * BOXF];          // coalesced staging (3.5 KB)

    const int bpb = gridDim.x / BATCHES;     // 64
    const int b   = blockIdx.x / bpb;
    const int blk = blockIdx.x % bpb;
    const int t   = threadIdx.x;

    const float inv_cell  = (float)GRIDW / 100.0f;   // 0.32
    const float cell_sz   = 100.0f / (float)GRIDW;   // 3.125
    const float cell_half = 0.5f * cell_sz;          // 1.5625
    const float org       = -50.0f;

    // ---- hoisted: issue point loads FIRST so their latency overlaps the
    //      table build (ptxas will not hoist LDG across the barrier itself).
    const int i0 = (blk * TPB + t) * PPT;
    const float2* p2 = reinterpret_cast<const float2*>(pts + ((size_t)b * N + i0) * 3);
    float2 qa = p2[0], qb = p2[1], qc = p2[2];

    // Zero counters + coalesced box staging.
    {
        if (t < NCELL / 4) {
            int4 zz = make_int4(0, 0, 0, 0);
            reinterpret_cast<int4*>(cnt)[t] = zz;
        }
        const float* src = boxes + (size_t)b * MBOX * BOXF;
        #pragma unroll
        for (int k = t; k < MBOX * BOXF; k += TPB)
            sRaw[k] = src[k];
    }
    __syncthreads();

    // ---- build: FOUR threads per box (row range split 4 ways).
    //      SAT-exact registration: AABB candidate cells are kept only if the
    //      rotated rect actually intersects the cell (two rect-axis tests;
    //      the x/y-axis tests are implied by the AABB range). A box that
    //      contains a point in cell C intersects C, and thresholds carry
    //      +1e-3 m slack >> fp error, so no containing box is ever dropped.
    {
        const int boxm   = t & (MBOX - 1);        // t % 128
        const int quarid = t >> 7;                // 0..3: row-range quarter
        const float* bx = &sRaw[boxm * BOXF];
        float cx = bx[0], cy = bx[1], cz = bx[2];
        float hx = 0.5f * bx[3], hy = 0.5f * bx[4], hz = 0.5f * bx[5];
        float s, c;
        __sincosf(bx[6], &s, &c);
        if (quarid == 0) {
            sA[boxm] = make_float4(cx, cy, c, s);
            sB[boxm] = make_float4(hx, hy, cz, hz);
        }

        float ac = fabsf(c), as = fabsf(s);
        float ex = hx * ac + hy * as + 1e-3f;
        float ey = hx * as + hy * ac + 1e-3f;
        float rc = cell_half * (ac + as);         // cell half-extent on rect axes
        float thu = hx + rc + 1e-3f;
        float thv = hy + rc + 1e-3f;

        int xlo = min(max((int)floorf((cx - ex - org) * inv_cell), 0), GRIDW - 1);
        int xhi = min(max((int)floorf((cx + ex - org) * inv_cell), 0), GRIDW - 1);
        int ylo = min(max((int)floorf((cy - ey - org) * inv_cell), 0), GRIDW - 1);
        int yhi = min(max((int)floorf((cy + ey - org) * inv_cell), 0), GRIDW - 1);

        // Split rows among the four threads handling this box.
        int nrows = yhi - ylo + 1;                // 1..GRIDW
        int per   = (nrows + 3) >> 2;             // ceil(nrows/4)
        int y0 = ylo + quarid * per;
        int y1 = min(y0 + per - 1, yhi);

        for (int yy = y0; yy <= y1; ++yy) {
            float qcy = org + ((float)yy + 0.5f) * cell_sz;
            float ddy = qcy - cy;
            for (int xx = xlo; xx <= xhi; ++xx) {
                float qcx = org + ((float)xx + 0.5f) * cell_sz;
                float ddx = qcx - cx;
                // Rect-axis SAT tests (u=(c,s), v=(-s,c)).
                float du = ddx * c + ddy * s;
                float dv = ddy * c - ddx * s;
                if ((fabsf(du) <= thu) & (fabsf(dv) <= thv)) {
                    int cell = yy * GRIDW + xx;
                    int pp = atomicAdd(&cnt[cell], 1);
                    if (pp < CAP) lst[cell][pp] = (unsigned char)boxm;
                }
            }
        }
    }

    // Cell indices computed from already-arrived registers (overlaps build).
    float x0 = qa.x, y0p = qa.y, z0 = qb.x;
    float x1 = qb.y, y1p = qc.x, z1 = qc.y;

    int ix0 = min(max((int)floorf((x0 - org) * inv_cell), 0), GRIDW - 1);
    int iy0 = min(max((int)floorf((y0p - org) * inv_cell), 0), GRIDW - 1);
    int ix1 = min(max((int)floorf((x1 - org) * inv_cell), 0), GRIDW - 1);
    int iy1 = min(max((int)floorf((y1p - org) * inv_cell), 0), GRIDW - 1);
    int cell0 = iy0 * GRIDW + ix0;
    int cell1 = iy1 * GRIDW + ix1;

    __syncthreads();

    // ---- query: two points per thread, interleaved, guard-free ----
    // Safety: evaluating the exact test against ANY box index is correct-
    // neutral (a true hit implies the box is in the point's cell list, so
    // min() is unchanged; a false hit contributes nothing). Hence entries
    // past a cell's count may be garbage; we only clamp to &127 for bounds.
    int n0 = cnt[cell0];
    int n1 = cnt[cell1];

    int l0 = (n0 <= CAP) ? n0 : 0;
    int l1 = (n1 <= CAP) ? n1 : 0;
    int nmax = (max(l0, l1) + 1) & ~1;            // <= CAP, multiple of 2

    int best0 = MBOX, best1 = MBOX;

    for (int j = 0; j < nmax; j += 2) {
        unsigned short u0 = *reinterpret_cast<const unsigned short*>(&lst[cell0][j]);
        unsigned short u1 = *reinterpret_cast<const unsigned short*>(&lst[cell1][j]);
        #pragma unroll
        for (int k = 0; k < 2; ++k) {
            {
                int m = (u0 >> (8 * k)) & 127;
                float4 A  = sA[m];
                float4 Bv = sB[m];
                float dx = x0 - A.x, dy = y0p - A.y, dz = z0 - Bv.z;
                float lx = dx * A.z + dy * A.w;
                float ly = dy * A.z - dx * A.w;
                bool in = (fabsf(lx) <= Bv.x) & (fabsf(ly) <= Bv.y) & (fabsf(dz) <= Bv.w);
                best0 = min(best0, in ? m : MBOX);
            }
            {
                int m = (u1 >> (8 * k)) & 127;
                float4 A  = sA[m];
                float4 Bv = sB[m];
                float dx = x1 - A.x, dy = y1p - A.y, dz = z1 - Bv.z;
                float lx = dx * A.z + dy * A.w;
                float ly = dy * A.z - dx * A.w;
                bool in = (fabsf(lx) <= Bv.x) & (fabsf(ly) <= Bv.y) & (fabsf(dz) <= Bv.w);
                best1 = min(best1, in ? m : MBOX);
            }
        }
    }

    // Structural overflow fallback: test every box (never skips a hit).
    if ((n0 > CAP) | (n1 > CAP)) {
        for (int m = 0; m < MBOX; ++m) {
            float4 A  = sA[m];
            float4 Bv = sB[m];
            if (n0 > CAP) {
                float dx = x0 - A.x, dy = y0p - A.y, dz = z0 - Bv.z;
                float lx = dx * A.z + dy * A.w;
                float ly = dy * A.z - dx * A.w;
                bool in = (fabsf(lx) <= Bv.x) & (fabsf(ly) <= Bv.y) & (fabsf(dz) <= Bv.w);
                best0 = min(best0, in ? m : MBOX);
            }
            if (n1 > CAP) {
                float dx = x1 - A.x, dy = y1p - A.y, dz = z1 - Bv.z;
                float lx = dx * A.z + dy * A.w;
                float ly = dy * A.z - dx * A.w;
                bool in = (fabsf(lx) <= Bv.x) & (fabsf(ly) <= Bv.y) & (fabsf(dz) <= Bv.w);
                best1 = min(best1, in ? m : MBOX);
            }
        }
    }

    float2 o = make_float2((best0 == MBOX) ? -1.0f : (float)best0,
                           (best1 == MBOX) ? -1.0f : (float)best1);
    *reinterpret_cast<float2*>(out + (size_t)b * N + i0) = o;
}

extern "C" void kernel_launch(void* const* d_in, const int* in_sizes, int n_in,
                              void* d_out, int out_size)
{
    const float* pts   = (const float*)d_in[0];
    const float* boxes = (const float*)d_in[1];
    float* out = (float*)d_out;

    const int N = out_size / BATCHES;                 // 65536
    const int grid = BATCHES * (N / (TPB * PPT));     // 4 * 64 = 256 blocks
    pib_fused<<<grid, TPB>>>(pts, boxes, out, N);
}